// round 12
// baseline (speedup 1.0000x reference)
#include <cuda_runtime.h>
#include <cuda_fp16.h>
#include <cstdint>

#define MDIM 16384
#define NDIM 1024
#define KDIM 4096

#define BM 128
#define BN 128
#define BK 64
#define NSTAGE 3
#define KT (KDIM / BK)              // 64 k-tiles
#define NTILES ((MDIM / BM) * (NDIM / BN))   // 1024 tiles
#define GRID 296                    // 148 SMs x 2 persistent CTAs
#define NMB (MDIM / BM)             // 128 H m-blocks
#define PRE 48                      // m-blocks converted in prologue
#define NWCTA (GRID - PRE)          // 248 CTAs quantize W
#define SSTRIDE 72                  // halves per smem row (64 + 8 pad)
#define ROWB (SSTRIDE * 2)          // 144 B
#define A_STAGE_B (BM * ROWB)       // 18432
#define STAGE_B   (2 * A_STAGE_B)   // 36864
#define HDR 1056
#define SMEM_BYTES (HDR + NSTAGE * STAGE_B)   // 111648 (x2 CTAs fits 228KB)

// ---------------- device scratch ----------------
__device__ __align__(16) uint16_t g_h[(size_t)MDIM * KDIM];   // fp16 hidden (128 MB)
__device__ __align__(16) uint16_t g_w[(size_t)NDIM * KDIM];   // fp16 w_int  (8 MB)
__device__ float g_scale[NDIM];
__device__ unsigned g_flag[NMB];
__device__ unsigned g_wctr;
__device__ unsigned g_tile_ctr;

// ---------------- PTX helpers ----------------
__device__ __forceinline__ uint32_t smem_u32(const void* p) {
    uint32_t a;
    asm("{ .reg .u64 t; cvta.to.shared.u64 t, %1; cvt.u32.u64 %0, t; }" : "=r"(a) : "l"(p));
    return a;
}
__device__ __forceinline__ void cp16(uint32_t dst, const void* src) {
    asm volatile("cp.async.cg.shared.global [%0], [%1], 16;" :: "r"(dst), "l"(src));
}
__device__ __forceinline__ void cp_commit() {
    asm volatile("cp.async.commit_group;" ::: "memory");
}
template <int N> __device__ __forceinline__ void cp_wait() {
    asm volatile("cp.async.wait_group %0;" :: "n"(N) : "memory");
}
__device__ __forceinline__ void ldsm4(uint32_t& r0, uint32_t& r1, uint32_t& r2, uint32_t& r3,
                                      uint32_t addr) {
    asm volatile("ldmatrix.sync.aligned.m8n8.x4.shared.b16 {%0,%1,%2,%3}, [%4];"
                 : "=r"(r0), "=r"(r1), "=r"(r2), "=r"(r3) : "r"(addr));
}
__device__ __forceinline__ void mma16816(float& d0, float& d1, float& d2, float& d3,
                                         uint32_t a0, uint32_t a1, uint32_t a2, uint32_t a3,
                                         uint32_t b0, uint32_t b1) {
    asm volatile(
        "mma.sync.aligned.m16n8k16.row.col.f32.f16.f16.f32 "
        "{%0,%1,%2,%3}, {%4,%5,%6,%7}, {%8,%9}, {%0,%1,%2,%3};"
        : "+f"(d0), "+f"(d1), "+f"(d2), "+f"(d3)
        : "r"(a0), "r"(a1), "r"(a2), "r"(a3), "r"(b0), "r"(b1));
}

// ---------------- init kernel: reset flags/counters (every launch/replay) ----------------
__global__ void init_kernel() {
    int tid = threadIdx.x;
    if (tid < NMB) g_flag[tid] = 0u;
    if (tid == 0) { g_wctr = 0u; g_tile_ctr = 0u; }
}

// ---------------- producers ----------------
// Convert one 128-row m-block of H to fp16 (whole CTA), then publish its flag.
__device__ void convert_block(const float* __restrict__ H, int mb) {
    int tid = threadIdx.x;
    const float4* src = reinterpret_cast<const float4*>(H) + (size_t)mb * (BM * KDIM / 4);
    uint2* dst = reinterpret_cast<uint2*>(g_h) + (size_t)mb * (BM * KDIM / 4);
    #pragma unroll 4
    for (int i = tid; i < BM * KDIM / 4; i += 256) {
        float4 v = src[i];
        __half2 lo = __floats2half2_rn(v.x, v.y);
        __half2 hi = __floats2half2_rn(v.z, v.w);
        uint2 o;
        o.x = *reinterpret_cast<uint32_t*>(&lo);
        o.y = *reinterpret_cast<uint32_t*>(&hi);
        dst[i] = o;
    }
    __threadfence();
    __syncthreads();
    if (tid == 0) *((volatile unsigned*)&g_flag[mb]) = 1u;
}

// Quantize one W output-channel row (whole CTA).
__device__ void quant_w_row(const float* __restrict__ W, int d) {
    int tid = threadIdx.x;
    const float4* row4 = reinterpret_cast<const float4*>(W + (size_t)d * KDIM);
    float4 f[4];
    float m = 0.f;
    #pragma unroll
    for (int i = 0; i < 4; i++) {
        f[i] = row4[i * 256 + tid];
        m = fmaxf(m, fmaxf(fmaxf(fabsf(f[i].x), fabsf(f[i].y)),
                           fmaxf(fabsf(f[i].z), fabsf(f[i].w))));
    }
    #pragma unroll
    for (int o = 16; o; o >>= 1) m = fmaxf(m, __shfl_xor_sync(0xffffffffu, m, o));
    __shared__ float red[8];
    if ((tid & 31) == 0) red[tid >> 5] = m;
    __syncthreads();
    if (tid < 8) {
        float v = red[tid];
        #pragma unroll
        for (int o = 4; o; o >>= 1) v = fmaxf(v, __shfl_xor_sync(0xffu, v, o));
        if (tid == 0) red[0] = v;
    }
    __syncthreads();
    float scale = fmaxf(red[0], 1e-8f) / 127.f;
    if (tid == 0) g_scale[d] = scale;
    uint2* wout = reinterpret_cast<uint2*>(g_w + (size_t)d * KDIM);
    #pragma unroll
    for (int i = 0; i < 4; i++) {
        float qx = fminf(fmaxf(rintf(f[i].x / scale), -128.f), 127.f);
        float qy = fminf(fmaxf(rintf(f[i].y / scale), -128.f), 127.f);
        float qz = fminf(fmaxf(rintf(f[i].z / scale), -128.f), 127.f);
        float qw = fminf(fmaxf(rintf(f[i].w / scale), -128.f), 127.f);
        __half2 lo = __floats2half2_rn(qx, qy);        // exact ints in fp16
        __half2 hi = __floats2half2_rn(qz, qw);
        uint2 o;
        o.x = *reinterpret_cast<uint32_t*>(&lo);
        o.y = *reinterpret_cast<uint32_t*>(&hi);
        wout[i * 256 + tid] = o;
    }
    __syncthreads();   // red[] reuse safety across rows
}

// ---------------- GEMM tile machinery (R4 schedule) ----------------
__device__ __forceinline__ void load_stage(uint32_t stage_base, int tid, int m0, int n0, int t) {
    int k0 = t * BK;
    const __half* Ab = reinterpret_cast<const __half*>(g_h) + (size_t)m0 * KDIM + k0;
    #pragma unroll
    for (int i = 0; i < 4; i++) {
        int cid = i * 256 + tid;
        int row = cid >> 3, col = cid & 7;
        cp16(stage_base + row * ROWB + col * 16, Ab + (size_t)row * KDIM + col * 8);
    }
    const __half* Bb = reinterpret_cast<const __half*>(g_w) + (size_t)n0 * KDIM + k0;
    uint32_t bbase = stage_base + A_STAGE_B;
    #pragma unroll
    for (int i = 0; i < 4; i++) {
        int cid = i * 256 + tid;
        int row = cid >> 3, col = cid & 7;
        cp16(bbase + row * ROWB + col * 16, Bb + (size_t)row * KDIM + col * 8);
    }
}

__global__ void __launch_bounds__(256, 2) fused_kernel(const float* __restrict__ H,
                                                       const float* __restrict__ W,
                                                       const float* __restrict__ bias,
                                                       const float* __restrict__ input,
                                                       float* __restrict__ out) {
    extern __shared__ char smem[];
    uint32_t sb = smem_u32(smem);
    int tid = threadIdx.x;
    int bid = blockIdx.x;
    int wid = tid >> 5, lane = tid & 31;
    int g = lane >> 2, c = lane & 3;
    int wm = wid & 1, wn = wid >> 1;      // 2 x 4 warp grid, warp tile 64x32

    float* s_scale = reinterpret_cast<float*>(smem);
    float* s_bias  = reinterpret_cast<float*>(smem + 512);
    unsigned* s_tile = reinterpret_cast<unsigned*>(smem + 1024);

    uint32_t a_loff = (uint32_t)((wm * 64 + (lane & 15)) * ROWB + (lane >> 4) * 16);
    uint32_t b_loff = (uint32_t)(A_STAGE_B +
                      (wn * 32 + (lane >> 4) * 8 + (lane & 7)) * ROWB +
                      (((lane >> 3) & 1) * 16));

    // ---- phase 0: producers ----
    if (bid < PRE) {
        convert_block(H, bid);            // blocks 0..PRE-1 ready early
    } else {
        for (int r = bid - PRE; r < NDIM; r += NWCTA) quant_w_row(W, r);
        __threadfence();
        __syncthreads();
        if (tid == 0) atomicAdd(&g_wctr, 1u);
    }

    // ---- phase 1: wait W fully quantized ----
    if (tid == 0) {
        while (*((volatile unsigned*)&g_wctr) < NWCTA) { }
        __threadfence();
    }
    __syncthreads();

    // ---- phase 2: persistent tile sweep with pipelined H conversion ----
    while (true) {
        __syncthreads();                  // prior tile fully done (epilogue reads)
        if (tid == 0) *s_tile = atomicAdd(&g_tile_ctr, 1u);
        __syncthreads();
        unsigned tile = *s_tile;
        if (tile >= NTILES) break;

        int mt = (int)(tile >> 3);
        int nt_ = (int)(tile & 7);
        int m0 = mt * BM, n0 = nt_ * BN;

        // conversion duty: block m = mt + PRE, owned by n-slot (m & 7)
        int mdy = mt + PRE;
        if (mdy < NMB && nt_ == (mdy & 7)) convert_block(H, mdy);

        // wait for this tile's A block
        if (tid == 0) {
            while (*((volatile unsigned*)&g_flag[mt]) == 0u) { }
            __threadfence();
        }
        if (tid < 128) {
            s_scale[tid] = g_scale[n0 + tid];
            s_bias[tid]  = bias[n0 + tid];
        }
        __syncthreads();

        // prologue: fill 3 stages
        #pragma unroll
        for (int s = 0; s < NSTAGE; s++) {
            load_stage(sb + HDR + (uint32_t)s * STAGE_B, tid, m0, n0, s);
            cp_commit();
        }

        float acc[4][4][4];
        #pragma unroll
        for (int mt2 = 0; mt2 < 4; mt2++)
            #pragma unroll
            for (int nt2 = 0; nt2 < 4; nt2++)
                #pragma unroll
                for (int r = 0; r < 4; r++) acc[mt2][nt2][r] = 0.f;

        for (int t = 0; t < KT; t++) {
            uint32_t stage = sb + HDR + (uint32_t)(t % NSTAGE) * STAGE_B;

            cp_wait<NSTAGE - 1>();
            __syncthreads();

            #pragma unroll
            for (int ks = 0; ks < 4; ks++) {
                uint32_t a[4][4], b[2][4];
                #pragma unroll
                for (int mt2 = 0; mt2 < 4; mt2++)
                    ldsm4(a[mt2][0], a[mt2][1], a[mt2][2], a[mt2][3],
                          stage + a_loff + (uint32_t)(mt2 * 16 * ROWB) + (uint32_t)(ks * 32));
                #pragma unroll
                for (int p = 0; p < 2; p++)
                    ldsm4(b[p][0], b[p][1], b[p][2], b[p][3],
                          stage + b_loff + (uint32_t)(p * 16 * ROWB) + (uint32_t)(ks * 32));
                #pragma unroll
                for (int mt2 = 0; mt2 < 4; mt2++)
                    #pragma unroll
                    for (int nt2 = 0; nt2 < 4; nt2++) {
                        int p = nt2 >> 1, q = nt2 & 1;
                        mma16816(acc[mt2][nt2][0], acc[mt2][nt2][1],
                                 acc[mt2][nt2][2], acc[mt2][nt2][3],
                                 a[mt2][0], a[mt2][1], a[mt2][2], a[mt2][3],
                                 b[p][2 * q], b[p][2 * q + 1]);
                    }
            }

            __syncthreads();
            if (t + NSTAGE < KT)
                load_stage(stage, tid, m0, n0, t + NSTAGE);
            cp_commit();
        }

        // epilogue: out = acc * scale[n] + bias[n] + input
        #pragma unroll
        for (int mt2 = 0; mt2 < 4; mt2++) {
            #pragma unroll
            for (int nt2 = 0; nt2 < 4; nt2++) {
                int nl = wn * 32 + nt2 * 8 + 2 * c;
                int n  = n0 + nl;
                float sc0 = s_scale[nl], sc1 = s_scale[nl + 1];
                float bi0 = s_bias[nl],  bi1 = s_bias[nl + 1];
                int mA = m0 + wm * 64 + mt2 * 16 + g;
                int mB = mA + 8;

                const float2* inA = reinterpret_cast<const float2*>(input + (size_t)mA * NDIM + n);
                const float2* inB = reinterpret_cast<const float2*>(input + (size_t)mB * NDIM + n);
                float2* outA = reinterpret_cast<float2*>(out + (size_t)mA * NDIM + n);
                float2* outB = reinterpret_cast<float2*>(out + (size_t)mB * NDIM + n);

                float2 ia = *inA, ib = *inB, oa, ob;
                oa.x = acc[mt2][nt2][0] * sc0 + bi0 + ia.x;
                oa.y = acc[mt2][nt2][1] * sc1 + bi1 + ia.y;
                ob.x = acc[mt2][nt2][2] * sc0 + bi0 + ib.x;
                ob.y = acc[mt2][nt2][3] * sc1 + bi1 + ib.y;
                *outA = oa;
                *outB = ob;
            }
        }
    }
}

// ---------------- launch ----------------
extern "C" void kernel_launch(void* const* d_in, const int* in_sizes, int n_in,
                              void* d_out, int out_size) {
    const float* hidden = (const float*)d_in[0];   // [16,1024,4096]
    const float* input  = (const float*)d_in[1];   // [16,1024,1024]
    const float* W      = (const float*)d_in[2];   // [1024,4096]
    const float* b      = (const float*)d_in[3];   // [1024]
    float* out = (float*)d_out;

    init_kernel<<<1, 256>>>();

    cudaFuncSetAttribute(fused_kernel, cudaFuncAttributeMaxDynamicSharedMemorySize, SMEM_BYTES);
    fused_kernel<<<GRID, 256, SMEM_BYTES>>>(hidden, W, b, input, out);
}

// round 13
// speedup vs baseline: 1.7174x; 1.7174x over previous
#include <cuda_runtime.h>
#include <cuda_fp16.h>
#include <cstdint>

#define MDIM 16384
#define NDIM 1024
#define KDIM 4096

#define BM 128
#define BN 128
#define BK 64
#define NSTAGE 3
#define KT (KDIM / BK)              // 64 k-tiles
#define NTILES ((MDIM / BM) * (NDIM / BN))   // 1024 tiles
#define GRID 296                    // 148 SMs x 2 persistent CTAs
#define NMB (MDIM / BM)             // 128 H m-blocks
#define LOOKAHEAD 48                // duty converts block mt+LOOKAHEAD
#define SSTRIDE 72
#define ROWB (SSTRIDE * 2)          // 144 B
#define A_STAGE_B (BM * ROWB)       // 18432
#define STAGE_B   (2 * A_STAGE_B)   // 36864
#define HDR 1056
#define SMEM_BYTES (HDR + NSTAGE * STAGE_B)   // 111648 (x2 CTAs fits 228KB)

// ---------------- device scratch ----------------
__device__ __align__(16) uint16_t g_h[(size_t)MDIM * KDIM];   // fp16 hidden (128 MB)
__device__ __align__(16) uint16_t g_w[(size_t)NDIM * KDIM];   // fp16 w_int  (8 MB)
__device__ float g_scale[NDIM];
__device__ unsigned g_cnt[NMB];     // per-block slice counters (ready when == 8)
__device__ unsigned g_wctr;         // CTAs finished phase 0
__device__ unsigned g_tile_ctr;

// ---------------- PTX helpers ----------------
__device__ __forceinline__ uint32_t smem_u32(const void* p) {
    uint32_t a;
    asm("{ .reg .u64 t; cvta.to.shared.u64 t, %1; cvt.u32.u64 %0, t; }" : "=r"(a) : "l"(p));
    return a;
}
__device__ __forceinline__ void cp16(uint32_t dst, const void* src) {
    asm volatile("cp.async.cg.shared.global [%0], [%1], 16;" :: "r"(dst), "l"(src));
}
__device__ __forceinline__ void cp_commit() {
    asm volatile("cp.async.commit_group;" ::: "memory");
}
template <int N> __device__ __forceinline__ void cp_wait() {
    asm volatile("cp.async.wait_group %0;" :: "n"(N) : "memory");
}
__device__ __forceinline__ void ldsm4(uint32_t& r0, uint32_t& r1, uint32_t& r2, uint32_t& r3,
                                      uint32_t addr) {
    asm volatile("ldmatrix.sync.aligned.m8n8.x4.shared.b16 {%0,%1,%2,%3}, [%4];"
                 : "=r"(r0), "=r"(r1), "=r"(r2), "=r"(r3) : "r"(addr));
}
__device__ __forceinline__ void mma16816(float& d0, float& d1, float& d2, float& d3,
                                         uint32_t a0, uint32_t a1, uint32_t a2, uint32_t a3,
                                         uint32_t b0, uint32_t b1) {
    asm volatile(
        "mma.sync.aligned.m16n8k16.row.col.f32.f16.f16.f32 "
        "{%0,%1,%2,%3}, {%4,%5,%6,%7}, {%8,%9}, {%0,%1,%2,%3};"
        : "+f"(d0), "+f"(d1), "+f"(d2), "+f"(d3)
        : "r"(a0), "r"(a1), "r"(a2), "r"(a3), "r"(b0), "r"(b1));
}

// ---------------- init kernel (runs each launch/replay) ----------------
__global__ void init_kernel() {
    int tid = threadIdx.x;
    if (tid < NMB) g_cnt[tid] = 0u;
    if (tid == 0) { g_wctr = 0u; g_tile_ctr = 0u; }
}

// ---------------- producers ----------------
// Convert one 16-row slice (p of 8) of H m-block mb. 16*4096 halves = 16384 float4.
__device__ void convert_slice(const float* __restrict__ H, int mb, int p) {
    int tid = threadIdx.x;
    size_t base = ((size_t)mb * BM + p * 16) * KDIM / 4;   // float4 index
    const float4* src = reinterpret_cast<const float4*>(H) + base;
    uint2* dst = reinterpret_cast<uint2*>(g_h) + base;
    #pragma unroll 8
    for (int i = tid; i < 16 * KDIM / 4; i += 256) {
        float4 v = src[i];
        __half2 lo = __floats2half2_rn(v.x, v.y);
        __half2 hi = __floats2half2_rn(v.z, v.w);
        uint2 o;
        o.x = *reinterpret_cast<uint32_t*>(&lo);
        o.y = *reinterpret_cast<uint32_t*>(&hi);
        dst[i] = o;
    }
}

// Quantize one W output-channel row (whole CTA).
__device__ void quant_w_row(const float* __restrict__ W, int d) {
    int tid = threadIdx.x;
    const float4* row4 = reinterpret_cast<const float4*>(W + (size_t)d * KDIM);
    float4 f[4];
    float m = 0.f;
    #pragma unroll
    for (int i = 0; i < 4; i++) {
        f[i] = row4[i * 256 + tid];
        m = fmaxf(m, fmaxf(fmaxf(fabsf(f[i].x), fabsf(f[i].y)),
                           fmaxf(fabsf(f[i].z), fabsf(f[i].w))));
    }
    #pragma unroll
    for (int o = 16; o; o >>= 1) m = fmaxf(m, __shfl_xor_sync(0xffffffffu, m, o));
    __shared__ float red[8];
    if ((tid & 31) == 0) red[tid >> 5] = m;
    __syncthreads();
    if (tid < 8) {
        float v = red[tid];
        #pragma unroll
        for (int o = 4; o; o >>= 1) v = fmaxf(v, __shfl_xor_sync(0xffu, v, o));
        if (tid == 0) red[0] = v;
    }
    __syncthreads();
    float scale = fmaxf(red[0], 1e-8f) / 127.f;
    if (tid == 0) g_scale[d] = scale;
    uint2* wout = reinterpret_cast<uint2*>(g_w + (size_t)d * KDIM);
    #pragma unroll
    for (int i = 0; i < 4; i++) {
        float qx = fminf(fmaxf(rintf(f[i].x / scale), -128.f), 127.f);
        float qy = fminf(fmaxf(rintf(f[i].y / scale), -128.f), 127.f);
        float qz = fminf(fmaxf(rintf(f[i].z / scale), -128.f), 127.f);
        float qw = fminf(fmaxf(rintf(f[i].w / scale), -128.f), 127.f);
        __half2 lo = __floats2half2_rn(qx, qy);        // exact ints in fp16
        __half2 hi = __floats2half2_rn(qz, qw);
        uint2 o;
        o.x = *reinterpret_cast<uint32_t*>(&lo);
        o.y = *reinterpret_cast<uint32_t*>(&hi);
        wout[i * 256 + tid] = o;
    }
    __syncthreads();   // red[] reuse safety across rows
}

// ---------------- GEMM stage load (R4 schedule) ----------------
__device__ __forceinline__ void load_stage(uint32_t stage_base, int tid, int m0, int n0, int t) {
    int k0 = t * BK;
    const __half* Ab = reinterpret_cast<const __half*>(g_h) + (size_t)m0 * KDIM + k0;
    #pragma unroll
    for (int i = 0; i < 4; i++) {
        int cid = i * 256 + tid;
        int row = cid >> 3, col = cid & 7;
        cp16(stage_base + row * ROWB + col * 16, Ab + (size_t)row * KDIM + col * 8);
    }
    const __half* Bb = reinterpret_cast<const __half*>(g_w) + (size_t)n0 * KDIM + k0;
    uint32_t bbase = stage_base + A_STAGE_B;
    #pragma unroll
    for (int i = 0; i < 4; i++) {
        int cid = i * 256 + tid;
        int row = cid >> 3, col = cid & 7;
        cp16(bbase + row * ROWB + col * 16, Bb + (size_t)row * KDIM + col * 8);
    }
}

__global__ void __launch_bounds__(256, 2) fused_kernel(const float* __restrict__ H,
                                                       const float* __restrict__ W,
                                                       const float* __restrict__ bias,
                                                       const float* __restrict__ input,
                                                       float* __restrict__ out) {
    extern __shared__ char smem[];
    uint32_t sb = smem_u32(smem);
    int tid = threadIdx.x;
    int bid = blockIdx.x;
    int wid = tid >> 5, lane = tid & 31;
    int g = lane >> 2, c = lane & 3;
    int wm = wid & 1, wn = wid >> 1;      // 2 x 4 warp grid, warp tile 64x32

    float* s_scale = reinterpret_cast<float*>(smem);
    float* s_bias  = reinterpret_cast<float*>(smem + 512);
    unsigned* s_tile = reinterpret_cast<unsigned*>(smem + 1024);

    uint32_t a_loff = (uint32_t)((wm * 64 + (lane & 15)) * ROWB + (lane >> 4) * 16);
    uint32_t b_loff = (uint32_t)(A_STAGE_B +
                      (wn * 32 + (lane >> 4) * 8 + (lane & 7)) * ROWB +
                      (((lane >> 3) & 1) * 16));

    // ---- phase 0: cooperative W quant + prologue H slices ----
    for (int r = bid; r < NDIM; r += GRID) quant_w_row(W, r);
    for (int s = bid; s < LOOKAHEAD * 8; s += GRID) {
        convert_slice(H, s >> 3, s & 7);
        __threadfence();
        __syncthreads();
        if (tid == 0) atomicAdd(&g_cnt[s >> 3], 1u);
        __syncthreads();
    }
    __threadfence();
    __syncthreads();
    if (tid == 0) atomicAdd(&g_wctr, 1u);

    // wait for all CTAs' phase 0 (W complete)
    if (tid == 0) {
        while (*((volatile unsigned*)&g_wctr) < GRID) { }
        __threadfence();
    }
    __syncthreads();

    // ---- phase 1: persistent tile sweep with pipelined duty conversion ----
    while (true) {
        __syncthreads();                  // prior tile done (s_scale/s_tile reuse)
        if (tid == 0) *s_tile = atomicAdd(&g_tile_ctr, 1u);
        __syncthreads();
        unsigned tile = *s_tile;
        if (tile >= NTILES) break;

        int mt = (int)(tile >> 3);
        int nt_ = (int)(tile & 7);
        int m0 = mt * BM, n0 = nt_ * BN;

        // duty: convert slice nt_ of block mt+LOOKAHEAD
        int bd = mt + LOOKAHEAD;
        if (bd < NMB) {
            convert_slice(H, bd, nt_);
            __threadfence();
            __syncthreads();
            if (tid == 0) atomicAdd(&g_cnt[bd], 1u);
        }

        // wait for this tile's A block (usually already ready)
        if (tid == 0) {
            while (*((volatile unsigned*)&g_cnt[mt]) < 8u) { }
            __threadfence();
        }
        if (tid < 128) {
            s_scale[tid] = g_scale[n0 + tid];
            s_bias[tid]  = bias[n0 + tid];
        }
        __syncthreads();

        // prologue: fill 3 stages
        #pragma unroll
        for (int s = 0; s < NSTAGE; s++) {
            load_stage(sb + HDR + (uint32_t)s * STAGE_B, tid, m0, n0, s);
            cp_commit();
        }

        float acc[4][4][4];
        #pragma unroll
        for (int mt2 = 0; mt2 < 4; mt2++)
            #pragma unroll
            for (int nt2 = 0; nt2 < 4; nt2++)
                #pragma unroll
                for (int r = 0; r < 4; r++) acc[mt2][nt2][r] = 0.f;

        for (int t = 0; t < KT; t++) {
            uint32_t stage = sb + HDR + (uint32_t)(t % NSTAGE) * STAGE_B;

            cp_wait<NSTAGE - 1>();
            __syncthreads();

            #pragma unroll
            for (int ks = 0; ks < 4; ks++) {
                uint32_t a[4][4], b[2][4];
                #pragma unroll
                for (int mt2 = 0; mt2 < 4; mt2++)
                    ldsm4(a[mt2][0], a[mt2][1], a[mt2][2], a[mt2][3],
                          stage + a_loff + (uint32_t)(mt2 * 16 * ROWB) + (uint32_t)(ks * 32));
                #pragma unroll
                for (int p = 0; p < 2; p++)
                    ldsm4(b[p][0], b[p][1], b[p][2], b[p][3],
                          stage + b_loff + (uint32_t)(p * 16 * ROWB) + (uint32_t)(ks * 32));
                #pragma unroll
                for (int mt2 = 0; mt2 < 4; mt2++)
                    #pragma unroll
                    for (int nt2 = 0; nt2 < 4; nt2++) {
                        int p = nt2 >> 1, q = nt2 & 1;
                        mma16816(acc[mt2][nt2][0], acc[mt2][nt2][1],
                                 acc[mt2][nt2][2], acc[mt2][nt2][3],
                                 a[mt2][0], a[mt2][1], a[mt2][2], a[mt2][3],
                                 b[p][2 * q], b[p][2 * q + 1]);
                    }
            }

            __syncthreads();
            if (t + NSTAGE < KT)
                load_stage(stage, tid, m0, n0, t + NSTAGE);
            cp_commit();
        }

        // epilogue: out = acc * scale[n] + bias[n] + input
        #pragma unroll
        for (int mt2 = 0; mt2 < 4; mt2++) {
            #pragma unroll
            for (int nt2 = 0; nt2 < 4; nt2++) {
                int nl = wn * 32 + nt2 * 8 + 2 * c;
                int n  = n0 + nl;
                float sc0 = s_scale[nl], sc1 = s_scale[nl + 1];
                float bi0 = s_bias[nl],  bi1 = s_bias[nl + 1];
                int mA = m0 + wm * 64 + mt2 * 16 + g;
                int mB = mA + 8;

                const float2* inA = reinterpret_cast<const float2*>(input + (size_t)mA * NDIM + n);
                const float2* inB = reinterpret_cast<const float2*>(input + (size_t)mB * NDIM + n);
                float2* outA = reinterpret_cast<float2*>(out + (size_t)mA * NDIM + n);
                float2* outB = reinterpret_cast<float2*>(out + (size_t)mB * NDIM + n);

                float2 ia = *inA, ib = *inB, oa, ob;
                oa.x = acc[mt2][nt2][0] * sc0 + bi0 + ia.x;
                oa.y = acc[mt2][nt2][1] * sc1 + bi1 + ia.y;
                ob.x = acc[mt2][nt2][2] * sc0 + bi0 + ib.x;
                ob.y = acc[mt2][nt2][3] * sc1 + bi1 + ib.y;
                *outA = oa;
                *outB = ob;
            }
        }
    }
}

// ---------------- launch ----------------
extern "C" void kernel_launch(void* const* d_in, const int* in_sizes, int n_in,
                              void* d_out, int out_size) {
    const float* hidden = (const float*)d_in[0];   // [16,1024,4096]
    const float* input  = (const float*)d_in[1];   // [16,1024,1024]
    const float* W      = (const float*)d_in[2];   // [1024,4096]
    const float* b      = (const float*)d_in[3];   // [1024]
    float* out = (float*)d_out;

    init_kernel<<<1, 256>>>();

    cudaFuncSetAttribute(fused_kernel, cudaFuncAttributeMaxDynamicSharedMemorySize, SMEM_BYTES);
    fused_kernel<<<GRID, 256, SMEM_BYTES>>>(hidden, W, b, input, out);
}